// round 1
// baseline (speedup 1.0000x reference)
#include <cuda_runtime.h>
#include <cuda_bf16.h>
#include <math.h>

// Shapes (fixed for this problem)
#define B_   128
#define Q_   16
#define D_   1024
#define E_   300
#define K_   11
#define TILE 256      // docs per tile (== blockDim)
#define NTILE (D_/TILE)
#define CH   100      // e-chunk size (25 float4, odd f4-stride -> conflict free)
#define NCH  (E_/CH)

#define QSTRIDE 304   // qn row stride in floats (76 float4)
#define SSTRIDE 272   // s_sh row stride (mod 32 == 16 -> conflict free half-warps)

// dynamic shared layout (floats):
//   qn      : 16*304              = 4864
//   docsh   : 256*100             = 25600   (union with s_sh: 16*272 = 4352)
//   res_sh  : 16*12               = 192
//   tmp16   : 16
#define SMEM_FLOATS (Q_*QSTRIDE + TILE*CH + Q_*12 + 16)

__global__ __launch_bounds__(256, 1)
void knrm_kernel(const int* __restrict__ doctoks,
                 const int* __restrict__ querytoks,
                 const float* __restrict__ emb,
                 const float* __restrict__ mus,
                 const float* __restrict__ sigmas,
                 const float* __restrict__ fc_w,
                 const float* __restrict__ fc_b,
                 float* __restrict__ out)
{
    extern __shared__ float sm[];
    float* qn     = sm;                       // 16 x 304
    float* docsh  = sm + Q_*QSTRIDE;          // 256 x 100  (aliased by s_sh)
    float* s_sh   = docsh;                    // 16 x 272
    float* res_sh = sm + Q_*QSTRIDE + TILE*CH;// 16 x 12
    float* tmp16  = res_sh + Q_*12;           // 16

    const int b   = blockIdx.x;
    const int tid = threadIdx.x;

    // ---------- load + normalize query embeddings into shared ----------
    for (int i = tid; i < Q_*E_; i += 256) {
        int q = i / E_, e = i - q*E_;
        int t = querytoks[b*Q_ + q];
        qn[q*QSTRIDE + e] = emb[t*E_ + e];
    }
    __syncthreads();
    {
        int q = tid >> 4, l = tid & 15;
        float ss = 0.f;
        for (int e = l; e < E_; e += 16) { float v = qn[q*QSTRIDE + e]; ss += v*v; }
        #pragma unroll
        for (int o = 8; o > 0; o >>= 1) ss += __shfl_down_sync(0xffffffffu, ss, o, 16);
        if (l == 0) tmp16[q] = 1.0f / (sqrtf(ss) + 1e-9f);
    }
    __syncthreads();
    for (int i = tid; i < Q_*E_; i += 256) {
        int q = i / E_, e = i - q*E_;
        qn[q*QSTRIDE + e] *= tmp16[q];
    }

    // ---------- persistent accumulators ----------
    float kacc[K_];
    #pragma unroll
    for (int k = 0; k < K_; k++) kacc[k] = 0.f;
    float simacc = 0.f;
    const int myq = tid >> 4, myl = tid & 15;

    for (int tile = 0; tile < NTILE; tile++) {
        const int dbase = tile*TILE;
        float acc[Q_];
        #pragma unroll
        for (int q = 0; q < Q_; q++) acc[q] = 0.f;
        float dd = 0.f;

        for (int ch = 0; ch < NCH; ch++) {
            __syncthreads();   // protect docsh (prev s_sh reads / prev chunk compute)
            const int ebase = ch*CH;
            for (int i = tid; i < TILE*CH; i += 256) {
                int r = i / CH, e = i - r*CH;
                int t = doctoks[b*D_ + dbase + r];
                docsh[r*CH + e] = emb[t*E_ + ebase + e];
            }
            __syncthreads();

            const float4* dv4 = reinterpret_cast<const float4*>(docsh + tid*CH);
            const float4* qv4 = reinterpret_cast<const float4*>(qn) + ch*(CH/4);
            #pragma unroll 5
            for (int e4 = 0; e4 < CH/4; e4++) {
                float4 d = dv4[e4];
                dd = fmaf(d.x,d.x, fmaf(d.y,d.y, fmaf(d.z,d.z, fmaf(d.w,d.w, dd))));
                #pragma unroll
                for (int q = 0; q < Q_; q++) {
                    float4 qv = qv4[q*(QSTRIDE/4) + e4];
                    acc[q] = fmaf(d.x,qv.x, fmaf(d.y,qv.y, fmaf(d.z,qv.z, fmaf(d.w,qv.w, acc[q]))));
                }
            }
        }

        // ---------- write s tile (aliases docsh; sync both sides) ----------
        float inv = 1.0f / (sqrtf(dd) + 1e-9f);
        __syncthreads();
        #pragma unroll
        for (int q = 0; q < Q_; q++) s_sh[q*SSTRIDE + tid] = acc[q]*inv;
        __syncthreads();

        // ---------- RBF kernel bank accumulation ----------
        float mu_r[K_], w_r[K_];
        #pragma unroll
        for (int k = 0; k < K_; k++) {
            mu_r[k] = mus[k];
            float sg = sigmas[k];
            w_r[k] = -0.5f/(sg*sg);
        }
        #pragma unroll 4
        for (int j = myl; j < TILE; j += 16) {
            float s = s_sh[myq*SSTRIDE + j];
            simacc += s;
            #pragma unroll
            for (int k = 0; k < K_; k++) {
                float dif = s - mu_r[k];
                kacc[k] += __expf(w_r[k]*dif*dif);
            }
        }
    }

    // ---------- reduce the 16 threads sharing a q ----------
    #pragma unroll
    for (int k = 0; k < K_; k++) {
        float v = kacc[k];
        #pragma unroll
        for (int o = 8; o > 0; o >>= 1) v += __shfl_down_sync(0xffffffffu, v, o, 16);
        kacc[k] = v;
    }
    {
        float v = simacc;
        #pragma unroll
        for (int o = 8; o > 0; o >>= 1) v += __shfl_down_sync(0xffffffffu, v, o, 16);
        simacc = v;
    }
    if (myl == 0) {
        bool m = (simacc != 0.0f);
        #pragma unroll
        for (int k = 0; k < K_; k++)
            res_sh[myq*12 + k] = m ? logf(kacc[k] + 1e-6f) : 0.0f;
    }
    __syncthreads();

    if (tid == 0) {
        float score = fc_b[0];
        #pragma unroll
        for (int k = 0; k < K_; k++) {
            float r = 0.f;
            for (int q = 0; q < Q_; q++) r += res_sh[q*12 + k];
            score = fmaf(r, fc_w[k], score);
        }
        out[b] = score;
    }
}

extern "C" void kernel_launch(void* const* d_in, const int* in_sizes, int n_in,
                              void* d_out, int out_size)
{
    const int*   doctoks   = (const int*)  d_in[0];
    const int*   querytoks = (const int*)  d_in[1];
    // d_in[2] = query_idf (unused by reference)
    const float* emb       = (const float*)d_in[3];
    const float* mus       = (const float*)d_in[4];
    const float* sigmas    = (const float*)d_in[5];
    const float* fc_w      = (const float*)d_in[6];
    const float* fc_b      = (const float*)d_in[7];
    float* out = (float*)d_out;

    static bool attr_set = false;
    if (!attr_set) {
        cudaFuncSetAttribute(knrm_kernel,
                             cudaFuncAttributeMaxDynamicSharedMemorySize,
                             SMEM_FLOATS * (int)sizeof(float));
        attr_set = true;
    }
    knrm_kernel<<<B_, 256, SMEM_FLOATS * (int)sizeof(float)>>>(
        doctoks, querytoks, emb, mus, sigmas, fc_w, fc_b, out);
}

// round 3
// speedup vs baseline: 3.0118x; 3.0118x over previous
#include <cuda_runtime.h>
#include <cuda_bf16.h>
#include <math.h>

#define B_    128
#define Q_    16
#define D_    1024
#define E_    300
#define K_    11
#define CTAS_PER_B 4
#define DOCS_PER_CTA (D_/CTAS_PER_B)   // 256
#define THREADS1 128
#define E4    (E_/4)                   // 75 float4
#define QSTRIDE 304                    // floats (76 f4)
#define SSTRIDE 264                    // mod 32 == 8 -> conflict-free 4x8 groups

// partials: [512 CTAs][16 q][13] (11 kacc + 1 simacc + pad)
__device__ float g_part[B_*CTAS_PER_B*Q_*13];

__global__ __launch_bounds__(THREADS1)
void knrm_part_kernel(const int* __restrict__ doctoks,
                      const int* __restrict__ querytoks,
                      const float* __restrict__ emb,
                      const float* __restrict__ mus,
                      const float* __restrict__ sigmas)
{
    __shared__ float sm[Q_*QSTRIDE + 16];
    float* qn    = sm;                // 16 x 304 ; later aliased as s_sh 16 x 264
    float* tmp16 = sm + Q_*QSTRIDE;

    const int tid   = threadIdx.x;
    const int b     = blockIdx.x >> 2;
    const int cta   = blockIdx.x & 3;
    const int dbase = cta * DOCS_PER_CTA;

    // ---- load + normalize query embeddings into shared ----
    for (int i = tid; i < Q_*E_; i += THREADS1) {
        int q = i / E_, e = i - q*E_;
        int t = querytoks[b*Q_ + q];
        qn[q*QSTRIDE + e] = emb[t*E_ + e];
    }
    __syncthreads();
    {
        // 128 threads: 16 q-rows x 8 lanes each
        int q = tid >> 3, l = tid & 7;
        float ss = 0.f;
        for (int e = l; e < E_; e += 8) { float v = qn[q*QSTRIDE + e]; ss += v*v; }
        #pragma unroll
        for (int o = 4; o > 0; o >>= 1) ss += __shfl_down_sync(0xffffffffu, ss, o, 8);
        if (l == 0) tmp16[q] = 1.0f / (sqrtf(ss) + 1e-9f);
    }
    __syncthreads();
    for (int i = tid; i < Q_*E_; i += THREADS1) {
        int q = i / E_, e = i - q*E_;
        qn[q*QSTRIDE + e] *= tmp16[q];
    }
    __syncthreads();

    // ---- dot products: 2 docs per thread, doc data streamed from global ----
    const int t0 = doctoks[b*D_ + dbase + tid];
    const int t1 = doctoks[b*D_ + dbase + tid + THREADS1];
    const float4* p0 = reinterpret_cast<const float4*>(emb) + (long)t0 * E4;
    const float4* p1 = reinterpret_cast<const float4*>(emb) + (long)t1 * E4;
    const float4* qn4 = reinterpret_cast<const float4*>(qn);

    float acc0[Q_], acc1[Q_];
    #pragma unroll
    for (int q = 0; q < Q_; q++) { acc0[q] = 0.f; acc1[q] = 0.f; }
    float dd0 = 0.f, dd1 = 0.f;

    #pragma unroll 5
    for (int e4 = 0; e4 < E4; e4++) {
        float4 a = p0[e4];
        float4 c = p1[e4];
        dd0 = fmaf(a.x,a.x, fmaf(a.y,a.y, fmaf(a.z,a.z, fmaf(a.w,a.w, dd0))));
        dd1 = fmaf(c.x,c.x, fmaf(c.y,c.y, fmaf(c.z,c.z, fmaf(c.w,c.w, dd1))));
        #pragma unroll
        for (int q = 0; q < Q_; q++) {
            float4 v = qn4[q*(QSTRIDE/4) + e4];
            acc0[q] = fmaf(a.x,v.x, fmaf(a.y,v.y, fmaf(a.z,v.z, fmaf(a.w,v.w, acc0[q]))));
            acc1[q] = fmaf(c.x,v.x, fmaf(c.y,v.y, fmaf(c.z,v.z, fmaf(c.w,v.w, acc1[q]))));
        }
    }

    const float inv0 = 1.0f / (sqrtf(dd0) + 1e-9f);
    const float inv1 = 1.0f / (sqrtf(dd1) + 1e-9f);

    // ---- transpose s into shared (aliases dead qn region) ----
    float* s_sh = sm;   // 16 x 264
    __syncthreads();    // all qn reads done
    #pragma unroll
    for (int q = 0; q < Q_; q++) {
        s_sh[q*SSTRIDE + tid]            = acc0[q] * inv0;
        s_sh[q*SSTRIDE + tid + THREADS1] = acc1[q] * inv1;
    }
    __syncthreads();

    // ---- RBF bank: 8 threads per q, each covers 32 docs ----
    const int myq = tid >> 3, myl = tid & 7;
    float mu_r[K_], w_r[K_];
    #pragma unroll
    for (int k = 0; k < K_; k++) {
        mu_r[k] = mus[k];
        float sg = sigmas[k];
        w_r[k] = -0.5f/(sg*sg);
    }
    float kacc[K_];
    #pragma unroll
    for (int k = 0; k < K_; k++) kacc[k] = 0.f;
    float simacc = 0.f;

    #pragma unroll 4
    for (int j = myl; j < DOCS_PER_CTA; j += 8) {
        float s = s_sh[myq*SSTRIDE + j];
        simacc += s;
        #pragma unroll
        for (int k = 0; k < K_; k++) {
            float dif = s - mu_r[k];
            kacc[k] += __expf(w_r[k]*dif*dif);
        }
    }

    // reduce over the 8 lanes of this q-group (contiguous lanes)
    #pragma unroll
    for (int k = 0; k < K_; k++) {
        float v = kacc[k];
        #pragma unroll
        for (int o = 4; o > 0; o >>= 1) v += __shfl_down_sync(0xffffffffu, v, o, 8);
        kacc[k] = v;
    }
    {
        float v = simacc;
        #pragma unroll
        for (int o = 4; o > 0; o >>= 1) v += __shfl_down_sync(0xffffffffu, v, o, 8);
        simacc = v;
    }
    if (myl == 0) {
        float* dst = &g_part[(blockIdx.x*Q_ + myq)*13];
        #pragma unroll
        for (int k = 0; k < K_; k++) dst[k] = kacc[k];
        dst[11] = simacc;
    }
}

__global__ __launch_bounds__(32)
void knrm_reduce_kernel(const float* __restrict__ fc_w,
                        const float* __restrict__ fc_b,
                        float* __restrict__ out)
{
    const int b = blockIdx.x;
    const int lane = threadIdx.x;
    const int q = lane & 15;          // lanes 16-31 duplicate, zeroed below
    const bool active = (lane < 16);

    float kb[K_];
    #pragma unroll
    for (int k = 0; k < K_; k++) kb[k] = 0.f;
    float sim = 0.f;
    #pragma unroll
    for (int c = 0; c < CTAS_PER_B; c++) {
        const float* src = &g_part[((b*CTAS_PER_B + c)*Q_ + q)*13];
        #pragma unroll
        for (int k = 0; k < K_; k++) kb[k] += src[k];
        sim += src[11];
    }
    const bool m = (sim != 0.0f) && active;
    float lg[K_];
    #pragma unroll
    for (int k = 0; k < K_; k++)
        lg[k] = m ? logf(kb[k] + 1e-6f) : 0.0f;

    float score = fc_b[0];
    #pragma unroll
    for (int k = 0; k < K_; k++) {
        float v = lg[k];
        #pragma unroll
        for (int o = 8; o > 0; o >>= 1) v += __shfl_down_sync(0xffffffffu, v, o, 16);
        score = fmaf(v, fc_w[k], score);
    }
    if (lane == 0) out[b] = score;
}

extern "C" void kernel_launch(void* const* d_in, const int* in_sizes, int n_in,
                              void* d_out, int out_size)
{
    const int*   doctoks   = (const int*)  d_in[0];
    const int*   querytoks = (const int*)  d_in[1];
    // d_in[2] = query_idf (unused)
    const float* emb       = (const float*)d_in[3];
    const float* mus       = (const float*)d_in[4];
    const float* sigmas    = (const float*)d_in[5];
    const float* fc_w      = (const float*)d_in[6];
    const float* fc_b      = (const float*)d_in[7];
    float* out = (float*)d_out;

    knrm_part_kernel<<<B_*CTAS_PER_B, THREADS1>>>(doctoks, querytoks, emb, mus, sigmas);
    knrm_reduce_kernel<<<B_, 32>>>(fc_w, fc_b, out);
}

// round 4
// speedup vs baseline: 3.1890x; 1.0588x over previous
#include <cuda_runtime.h>
#include <cuda_bf16.h>
#include <math.h>

#define B_    128
#define Q_    16
#define D_    1024
#define E_    300
#define K_    11
#define CTAS_PER_B 4
#define DOCS_PER_CTA (D_/CTAS_PER_B)   // 256
#define THREADS1 128
#define E4    (E_/4)                   // 75 float4
#define QSTRIDE 304                    // floats (76 f4)
#define SSTRIDE 264                    // mod 32 == 8 -> conflict-free 4x8 groups

// partials: [512 CTAs][16 q][13] (11 kacc + 1 simacc + pad)
__device__ float g_part[B_*CTAS_PER_B*Q_*13];
__device__ int   g_count[B_];          // zero-init; reset to 0 by last CTA each run

__global__ __launch_bounds__(THREADS1, 4)
void knrm_part_kernel(const int* __restrict__ doctoks,
                      const int* __restrict__ querytoks,
                      const float* __restrict__ emb,
                      const float* __restrict__ mus,
                      const float* __restrict__ sigmas,
                      const float* __restrict__ fc_w,
                      const float* __restrict__ fc_b,
                      float* __restrict__ out)
{
    __shared__ float sm[Q_*QSTRIDE + 16];
    __shared__ int last_flag;
    float* qn    = sm;                // 16 x 304 ; later aliased as s_sh 16 x 264
    float* tmp16 = sm + Q_*QSTRIDE;

    const int tid   = threadIdx.x;
    const int b     = blockIdx.x >> 2;
    const int cta   = blockIdx.x & 3;
    const int dbase = cta * DOCS_PER_CTA;

    // ---- load + normalize query embeddings into shared ----
    for (int i = tid; i < Q_*E_; i += THREADS1) {
        int q = i / E_, e = i - q*E_;
        int t = querytoks[b*Q_ + q];
        qn[q*QSTRIDE + e] = emb[t*E_ + e];
    }
    __syncthreads();
    {
        // 128 threads: 16 q-rows x 8 lanes each
        int q = tid >> 3, l = tid & 7;
        float ss = 0.f;
        for (int e = l; e < E_; e += 8) { float v = qn[q*QSTRIDE + e]; ss += v*v; }
        #pragma unroll
        for (int o = 4; o > 0; o >>= 1) ss += __shfl_down_sync(0xffffffffu, ss, o, 8);
        if (l == 0) tmp16[q] = 1.0f / (sqrtf(ss) + 1e-9f);
    }
    __syncthreads();
    for (int i = tid; i < Q_*E_; i += THREADS1) {
        int q = i / E_, e = i - q*E_;
        qn[q*QSTRIDE + e] *= tmp16[q];
    }
    __syncthreads();

    // ---- dot products: 2 docs/thread, doc rows streamed from global,
    //      1-step software prefetch to hide L2 latency ----
    const int t0 = doctoks[b*D_ + dbase + tid];
    const int t1 = doctoks[b*D_ + dbase + tid + THREADS1];
    const float4* p0 = reinterpret_cast<const float4*>(emb) + (long)t0 * E4;
    const float4* p1 = reinterpret_cast<const float4*>(emb) + (long)t1 * E4;
    const float4* qn4 = reinterpret_cast<const float4*>(qn);

    float acc0[Q_], acc1[Q_];
    #pragma unroll
    for (int q = 0; q < Q_; q++) { acc0[q] = 0.f; acc1[q] = 0.f; }
    float dd0 = 0.f, dd1 = 0.f;

    auto fmastep = [&](const float4 a, const float4 c, int e4) {
        dd0 = fmaf(a.x,a.x, fmaf(a.y,a.y, fmaf(a.z,a.z, fmaf(a.w,a.w, dd0))));
        dd1 = fmaf(c.x,c.x, fmaf(c.y,c.y, fmaf(c.z,c.z, fmaf(c.w,c.w, dd1))));
        #pragma unroll
        for (int q = 0; q < Q_; q++) {
            float4 v = qn4[q*(QSTRIDE/4) + e4];
            acc0[q] = fmaf(a.x,v.x, fmaf(a.y,v.y, fmaf(a.z,v.z, fmaf(a.w,v.w, acc0[q]))));
            acc1[q] = fmaf(c.x,v.x, fmaf(c.y,v.y, fmaf(c.z,v.z, fmaf(c.w,v.w, acc1[q]))));
        }
    };

    float4 a = p0[0];
    float4 c = p1[0];
    #pragma unroll 5
    for (int e4 = 0; e4 < E4-1; e4++) {
        float4 an = p0[e4+1];
        float4 cn = p1[e4+1];
        fmastep(a, c, e4);
        a = an; c = cn;
    }
    fmastep(a, c, E4-1);

    const float inv0 = 1.0f / (sqrtf(dd0) + 1e-9f);
    const float inv1 = 1.0f / (sqrtf(dd1) + 1e-9f);

    // ---- transpose s into shared (aliases dead qn region) ----
    float* s_sh = sm;   // 16 x 264
    __syncthreads();    // all qn reads done
    #pragma unroll
    for (int q = 0; q < Q_; q++) {
        s_sh[q*SSTRIDE + tid]            = acc0[q] * inv0;
        s_sh[q*SSTRIDE + tid + THREADS1] = acc1[q] * inv1;
    }
    __syncthreads();

    // ---- RBF bank: 8 threads per q, each covers 32 docs ----
    const int myq = tid >> 3, myl = tid & 7;
    float mu_r[K_], w_r[K_];
    #pragma unroll
    for (int k = 0; k < K_; k++) {
        mu_r[k] = mus[k];
        float sg = sigmas[k];
        w_r[k] = -0.5f/(sg*sg);
    }
    float kacc[K_];
    #pragma unroll
    for (int k = 0; k < K_; k++) kacc[k] = 0.f;
    float simacc = 0.f;

    #pragma unroll 4
    for (int j = myl; j < DOCS_PER_CTA; j += 8) {
        float s = s_sh[myq*SSTRIDE + j];
        simacc += s;
        #pragma unroll
        for (int k = 0; k < K_; k++) {
            float dif = s - mu_r[k];
            kacc[k] += __expf(w_r[k]*dif*dif);
        }
    }

    // reduce over the 8 lanes of this q-group (contiguous lanes)
    #pragma unroll
    for (int k = 0; k < K_; k++) {
        float v = kacc[k];
        #pragma unroll
        for (int o = 4; o > 0; o >>= 1) v += __shfl_down_sync(0xffffffffu, v, o, 8);
        kacc[k] = v;
    }
    {
        float v = simacc;
        #pragma unroll
        for (int o = 4; o > 0; o >>= 1) v += __shfl_down_sync(0xffffffffu, v, o, 8);
        simacc = v;
    }
    if (myl == 0) {
        float* dst = &g_part[(blockIdx.x*Q_ + myq)*13];
        #pragma unroll
        for (int k = 0; k < K_; k++) dst[k] = kacc[k];
        dst[11] = simacc;
    }

    // ---- fused finalization: last CTA of this batch reduces + scores ----
    __syncthreads();
    if (tid == 0) {
        __threadfence();                       // release our partials
        int old = atomicAdd(&g_count[b], 1);
        last_flag = (old == CTAS_PER_B - 1);
    }
    __syncthreads();
    if (!last_flag) return;

    if (tid < 32) {
        __threadfence();                       // acquire other CTAs' partials
        const int lane = tid;
        const int q = lane & 15;               // lanes 16-31 duplicate; masked below
        const bool active = (lane < 16);

        float kb[K_];
        #pragma unroll
        for (int k = 0; k < K_; k++) kb[k] = 0.f;
        float sim = 0.f;
        #pragma unroll
        for (int cc = 0; cc < CTAS_PER_B; cc++) {
            const float* src = &g_part[((b*CTAS_PER_B + cc)*Q_ + q)*13];
            #pragma unroll
            for (int k = 0; k < K_; k++) kb[k] += src[k];
            sim += src[11];
        }
        const bool m = (sim != 0.0f) && active;
        float score = fc_b[0];
        #pragma unroll
        for (int k = 0; k < K_; k++) {
            float v = m ? logf(kb[k] + 1e-6f) : 0.0f;
            #pragma unroll
            for (int o = 8; o > 0; o >>= 1) v += __shfl_down_sync(0xffffffffu, v, o, 16);
            score = fmaf(v, fc_w[k], score);
        }
        if (lane == 0) {
            out[b] = score;
            g_count[b] = 0;                    // reset for next run / replay
        }
    }
}

extern "C" void kernel_launch(void* const* d_in, const int* in_sizes, int n_in,
                              void* d_out, int out_size)
{
    const int*   doctoks   = (const int*)  d_in[0];
    const int*   querytoks = (const int*)  d_in[1];
    // d_in[2] = query_idf (unused)
    const float* emb       = (const float*)d_in[3];
    const float* mus       = (const float*)d_in[4];
    const float* sigmas    = (const float*)d_in[5];
    const float* fc_w      = (const float*)d_in[6];
    const float* fc_b      = (const float*)d_in[7];
    float* out = (float*)d_out;

    knrm_part_kernel<<<B_*CTAS_PER_B, THREADS1>>>(
        doctoks, querytoks, emb, mus, sigmas, fc_w, fc_b, out);
}